// round 4
// baseline (speedup 1.0000x reference)
#include <cuda_runtime.h>

// LSTM: B=1024, T=512, F=40, H=50 (4H=200 gates), + MLP head (50->10->1) + x[:,-1,0]
//
// Strategy: batch-parallel persistent recurrence. Each CTA owns RR=4 batch rows
// for all 512 timesteps. Combined weight W[200][90] = [W_ih | W_hh] lives in
// SMEM (gate-major, row stride padded to 92 floats = 368B -> conflict-free
// LDS.128 across lanes). Per step each thread j<200 computes its gate for all
// 4 rows from the combined z=[x_t | h_{t-1}] vector (broadcast LDS.128).
// c-state is register-resident (thread (r,u) ownership). x_{t+2} is prefetched
// from global into registers during step t's compute phase.

#define BB   1024
#define TT   512
#define FF   40
#define HH   50
#define GG   200      // 4*H
#define RR   4        // batch rows per CTA
#define KKP  92       // padded combined-K stride (90 used, 2 pad) -> 23 float4
#define NI   23       // KKP/4
#define NTH  256
#define NGRID (BB / RR)   // 256

__global__ __launch_bounds__(NTH, 2)
void lstm_fused_kernel(const float* __restrict__ x,
                       const float* __restrict__ Wih,
                       const float* __restrict__ Whh,
                       const float* __restrict__ bih,
                       const float* __restrict__ bhh,
                       const float* __restrict__ W1,
                       const float* __restrict__ b1,
                       const float* __restrict__ W2,
                       const float* __restrict__ b2,
                       float* __restrict__ out)
{
    extern __shared__ float sm[];
    float* sW = sm;                 // [GG][KKP]  = 18400 floats (73600 B)
    float* sZ = sW + GG * KKP;      // [RR][KKP]  =   368 floats  (z = [x_t | h])
    float* sB = sZ + RR * KKP;      // [GG]       combined bias
    float* sG = sB + GG;            // [RR][GG]   pre-activation gates

    const int tid = threadIdx.x;
    const int b0  = blockIdx.x * RR;

    // ---- init: combined weights (gate-major, padded), bias, zeroed z ----
    for (int i = tid; i < GG * KKP; i += NTH) {
        int j  = i / KKP;
        int kk = i - j * KKP;
        float v = 0.0f;
        if (kk < FF)            v = Wih[j * FF + kk];
        else if (kk < FF + HH)  v = Whh[j * HH + (kk - FF)];
        sW[i] = v;
    }
    for (int i = tid; i < GG; i += NTH)       sB[i] = bih[i] + bhh[i];
    for (int i = tid; i < RR * KKP; i += NTH) sZ[i] = 0.0f;   // h0 = 0, pads = 0
    __syncthreads();

    // ---- x loader role: RR*10 = 40 threads, each owns one float4 slot ----
    const int lr = tid / 10;           // row within CTA
    const int lq = tid - lr * 10;      // float4 index within the 40-float x row
    const float4* __restrict__ xv = (const float4*)x;
    float4 xn = make_float4(0.f, 0.f, 0.f, 0.f);
    if (tid < RR * 10) {
        int b = b0 + lr;
        float4 v0 = xv[(b * TT + 0) * 10 + lq];
        ((float4*)sZ)[lr * NI + lq] = v0;              // x_0 into z
        xn = xv[(b * TT + 1) * 10 + lq];               // prefetch x_1
    }

    // ---- c-state ownership: thread tid<200 owns (r = tid/50, u = tid%50) ----
    const int hr = tid / HH;
    const int hu = tid - hr * HH;
    float creg = 0.0f;
    if (tid < GG) creg = (hu == 0) ? 1.0f : 0.0f;      // c0[:,0] = 1

    const float4* __restrict__ wt4 = (const float4*)(sW + tid * KKP);
    const float4* __restrict__ z4  = (const float4*)sZ;
    const float biasj = (tid < GG) ? sB[tid] : 0.0f;
    __syncthreads();

    // ================= recurrence =================
    for (int t = 0; t < TT; ++t) {
        // Phase A: gates[r][j] = bias_j + z[r] . W[j]   (thread j, 4 rows)
        if (tid < GG) {
            float a0 = biasj, a1 = biasj, a2 = biasj, a3 = biasj;
            #pragma unroll
            for (int i = 0; i < NI; ++i) {
                float4 w  = wt4[i];
                float4 z0 = z4[0 * NI + i];
                float4 z1 = z4[1 * NI + i];
                float4 z2 = z4[2 * NI + i];
                float4 z3 = z4[3 * NI + i];
                a0 = fmaf(w.x, z0.x, a0); a0 = fmaf(w.y, z0.y, a0);
                a0 = fmaf(w.z, z0.z, a0); a0 = fmaf(w.w, z0.w, a0);
                a1 = fmaf(w.x, z1.x, a1); a1 = fmaf(w.y, z1.y, a1);
                a1 = fmaf(w.z, z1.z, a1); a1 = fmaf(w.w, z1.w, a1);
                a2 = fmaf(w.x, z2.x, a2); a2 = fmaf(w.y, z2.y, a2);
                a2 = fmaf(w.z, z2.z, a2); a2 = fmaf(w.w, z2.w, a2);
                a3 = fmaf(w.x, z3.x, a3); a3 = fmaf(w.y, z3.y, a3);
                a3 = fmaf(w.z, z3.z, a3); a3 = fmaf(w.w, z3.w, a3);
            }
            sG[0 * GG + tid] = a0;
            sG[1 * GG + tid] = a1;
            sG[2 * GG + tid] = a2;
            sG[3 * GG + tid] = a3;
        }
        __syncthreads();

        // Phase B: LSTM cell update for (r, u); write h into z's h-section
        if (tid < RR * HH) {
            float ig = sG[hr * GG +          hu];
            float fg = sG[hr * GG +     HH + hu];
            float gg = sG[hr * GG + 2 * HH + hu];
            float og = sG[hr * GG + 3 * HH + hu];
            float si = 1.0f / (1.0f + __expf(-ig));
            float sf = 1.0f / (1.0f + __expf(-fg));
            float tg = tanhf(gg);
            float so = 1.0f / (1.0f + __expf(-og));
            creg = fmaf(sf, creg, si * tg);
            sZ[hr * KKP + FF + hu] = so * tanhf(creg);
        }

        // Phase C: commit prefetched x_{t+1} into z; issue load of x_{t+2}
        if (tid < RR * 10 && (t + 1) < TT) {
            ((float4*)sZ)[lr * NI + lq] = xn;
            if ((t + 2) < TT)
                xn = xv[((b0 + lr) * TT + (t + 2)) * 10 + lq];
        }
        __syncthreads();
    }

    // ================= MLP head =================
    // hidden[r][m] = relu(b1[m] + h_T[r] . W1[m]),  40 work items
    if (tid < RR * 10) {
        float s = b1[lq];
        #pragma unroll
        for (int u = 0; u < HH; ++u)
            s = fmaf(sZ[lr * KKP + FF + u], W1[lq * HH + u], s);
        sG[lr * 10 + lq] = fmaxf(s, 0.0f);
    }
    __syncthreads();

    // out[b] = b2 + hidden[r] . W2 + x[b, T-1, 0]
    if (tid < RR) {
        int b = b0 + tid;
        float o = b2[0];
        #pragma unroll
        for (int m = 0; m < 10; ++m)
            o = fmaf(sG[tid * 10 + m], W2[m], o);
        o += x[(b * TT + (TT - 1)) * FF + 0];
        out[b] = o;
    }
}

extern "C" void kernel_launch(void* const* d_in, const int* in_sizes, int n_in,
                              void* d_out, int out_size)
{
    const float* x   = (const float*)d_in[0];
    const float* Wih = (const float*)d_in[1];
    const float* Whh = (const float*)d_in[2];
    const float* bih = (const float*)d_in[3];
    const float* bhh = (const float*)d_in[4];
    const float* W1  = (const float*)d_in[5];
    const float* b1  = (const float*)d_in[6];
    const float* W2  = (const float*)d_in[7];
    const float* b2  = (const float*)d_in[8];
    float* out = (float*)d_out;

    const int smem_bytes = (GG * KKP + RR * KKP + GG + RR * GG) * (int)sizeof(float); // 79072
    cudaFuncSetAttribute(lstm_fused_kernel,
                         cudaFuncAttributeMaxDynamicSharedMemorySize, smem_bytes);

    lstm_fused_kernel<<<NGRID, NTH, smem_bytes>>>(
        x, Wih, Whh, bih, bhh, W1, b1, W2, b2, out);
}

// round 5
// speedup vs baseline: 1.3288x; 1.3288x over previous
#include <cuda_runtime.h>

// LSTM B=1024 T=512 F=40 H=50 + MLP head, fused persistent kernel.
//
// 128 CTAs (1/SM), RR=8 batch rows per CTA, 512 threads:
//   tid 0..399   : gemv threads. (half = tid/200, gate j = tid%200). Each holds
//                  its 48-float K-half of combined W=[W_ih|W_hh] as 24 packed
//                  f32x2 registers; computes partial gate dot-products for all
//                  8 rows with fma.rn.f32x2 against broadcast z loads
//                  (ld.shared.v2.u64). Partials -> sP[half].
//                  Same threads then switch role to cell (r=tid/50, u=tid%50):
//                  sum partials (bias pre-folded into half0 acc init), apply
//                  MUFU tanh.approx activations, register-resident c, h -> sZ.
//   tid 400..479 : x prefetch (8 rows x 10 float4), 2 steps ahead.
// Two __syncthreads per step.

#define TT   512
#define FF   40
#define HH   50
#define GG   200          // 4*H
#define RR   8            // rows per CTA
#define KP   96           // padded combined K (40 x | 50 h | 6 pad)
#define NC   400          // compute threads
#define NTH  512
#define NGRID 128         // 1024 / RR

__device__ __forceinline__ unsigned long long pk2(float lo, float hi) {
    unsigned long long r;
    asm("mov.b64 %0, {%1, %2};" : "=l"(r) : "f"(lo), "f"(hi));
    return r;
}
__device__ __forceinline__ void upk2(unsigned long long v, float& lo, float& hi) {
    asm("mov.b64 {%0, %1}, %2;" : "=f"(lo), "=f"(hi) : "l"(v));
}
__device__ __forceinline__ unsigned long long f2fma(unsigned long long a,
                                                   unsigned long long b,
                                                   unsigned long long c) {
    unsigned long long d;
    asm("fma.rn.f32x2 %0, %1, %2, %3;" : "=l"(d) : "l"(a), "l"(b), "l"(c));
    return d;
}
__device__ __forceinline__ float tanh_f(float x) {
    float y;
    asm("tanh.approx.f32 %0, %1;" : "=f"(y) : "f"(x));
    return y;
}
__device__ __forceinline__ float sig_f(float x) {
    return fmaf(0.5f, tanh_f(0.5f * x), 0.5f);   // sigmoid(x)=0.5*tanh(x/2)+0.5
}

__device__ __forceinline__ float wfetch(const float* __restrict__ Wih,
                                        const float* __restrict__ Whh,
                                        int j, int k) {
    if (k < FF)       return Wih[j * FF + k];
    if (k < FF + HH)  return Whh[j * HH + (k - FF)];
    return 0.0f;
}

__global__ __launch_bounds__(NTH, 1)
void lstm_kernel(const float* __restrict__ x,   const float* __restrict__ Wih,
                 const float* __restrict__ Whh, const float* __restrict__ bih,
                 const float* __restrict__ bhh, const float* __restrict__ W1,
                 const float* __restrict__ b1,  const float* __restrict__ W2,
                 const float* __restrict__ b2,  float* __restrict__ out)
{
    __shared__ __align__(16) float sZ[RR][KP];       // z = [x_t | h | pad]
    __shared__ __align__(16) float sP[2][RR][GG];    // per-half gate partials

    const int tid = threadIdx.x;
    const int b0  = blockIdx.x * RR;

    // ---- zero z (h + pads; x region overwritten below) ----
    for (int i = tid; i < RR * KP; i += NTH) ((float*)sZ)[i] = 0.0f;
    __syncthreads();

    // ---- per-thread roles ----
    const int half = (tid < NC) ? (tid / GG) : 0;
    const int j    = (tid < NC) ? (tid - half * GG) : 0;
    const int cr   = tid / HH;          // cell row   (valid for tid<400)
    const int cu   = tid - cr * HH;     // cell unit

    // ---- register-resident weights (packed f32x2), bias folded into half0 ----
    unsigned long long w[24];
    unsigned long long bias0 = 0ull;
    if (tid < NC) {
        #pragma unroll
        for (int kk = 0; kk < 24; ++kk) {
            int k0 = half * 48 + 2 * kk;
            w[kk] = pk2(wfetch(Wih, Whh, j, k0), wfetch(Wih, Whh, j, k0 + 1));
        }
        if (half == 0) bias0 = pk2(bih[j] + bhh[j], 0.0f);
    } else {
        #pragma unroll
        for (int kk = 0; kk < 24; ++kk) w[kk] = 0ull;
    }

    // ---- c-state: cell (cr, cu) register-resident; c0[:,0] = 1 ----
    float creg = (tid < NC && cu == 0) ? 1.0f : 0.0f;

    // ---- x prefetch roles ----
    const int li = tid - NC;               // 0..79 loaders
    const int lr = li / 10, lq = li - (li / 10) * 10;
    const bool isload = (tid >= NC) && (li < RR * 10);
    const float4* __restrict__ xv = (const float4*)x;
    float4 xn = make_float4(0.f, 0.f, 0.f, 0.f);
    if (isload) {
        ((float4*)&sZ[lr][0])[lq] = xv[((b0 + lr) * TT + 0) * 10 + lq];  // x_0
        xn = xv[((b0 + lr) * TT + 1) * 10 + lq];                          // x_1
    }
    __syncthreads();

    // ================= recurrence =================
    for (int t = 0; t < TT; ++t) {
        // Phase A: partial gates, all 8 rows, this thread's K-half
        if (tid < NC) {
            unsigned long long acc[RR];
            #pragma unroll
            for (int r = 0; r < RR; ++r) acc[r] = bias0;    // 0 for half1
            const ulonglong2* __restrict__ zb =
                (const ulonglong2*)(&sZ[0][0]) + half * 12; // 24 ull2 per row
            #pragma unroll
            for (int i = 0; i < 12; ++i) {
                #pragma unroll
                for (int r = 0; r < RR; ++r) {
                    ulonglong2 z = zb[r * 24 + i];          // warp broadcast
                    acc[r] = f2fma(w[2 * i],     z.x, acc[r]);
                    acc[r] = f2fma(w[2 * i + 1], z.y, acc[r]);
                }
            }
            #pragma unroll
            for (int r = 0; r < RR; ++r) {
                float lo, hi; upk2(acc[r], lo, hi);
                sP[half][r][j] = lo + hi;
            }
        }
        __syncthreads();

        // Phase B: cell update (400 threads) + x commit/prefetch (80 threads)
        if (tid < NC) {
            float gi = sP[0][cr][cu]          + sP[1][cr][cu];
            float gf = sP[0][cr][HH + cu]     + sP[1][cr][HH + cu];
            float gc = sP[0][cr][2 * HH + cu] + sP[1][cr][2 * HH + cu];
            float go = sP[0][cr][3 * HH + cu] + sP[1][cr][3 * HH + cu];
            float si = sig_f(gi);
            float sf = sig_f(gf);
            float tg = tanh_f(gc);
            float so = sig_f(go);
            creg = fmaf(sf, creg, si * tg);
            sZ[cr][FF + cu] = so * tanh_f(creg);
        } else if (isload && (t + 1) < TT) {
            ((float4*)&sZ[lr][0])[lq] = xn;                 // commit x_{t+1}
            if ((t + 2) < TT)
                xn = xv[((b0 + lr) * TT + (t + 2)) * 10 + lq];
        }
        __syncthreads();
    }

    // ================= MLP head =================
    if (tid < RR * 10) {        // hidden[r][m] = relu(b1 + h.W1[m])
        int r = tid / 10, m = tid - (tid / 10) * 10;
        float s = b1[m];
        #pragma unroll
        for (int u = 0; u < HH; ++u)
            s = fmaf(sZ[r][FF + u], W1[m * HH + u], s);
        sP[0][0][tid] = fmaxf(s, 0.0f);
    }
    __syncthreads();

    if (tid < RR) {             // out[b] = b2 + hidden.W2 + x[b, T-1, 0]
        float o = b2[0];
        #pragma unroll
        for (int m = 0; m < 10; ++m)
            o = fmaf(sP[0][0][tid * 10 + m], W2[m], o);
        out[b0 + tid] = o + x[((b0 + tid) * TT + (TT - 1)) * FF + 0];
    }
}

extern "C" void kernel_launch(void* const* d_in, const int* in_sizes, int n_in,
                              void* d_out, int out_size)
{
    const float* x   = (const float*)d_in[0];
    const float* Wih = (const float*)d_in[1];
    const float* Whh = (const float*)d_in[2];
    const float* bih = (const float*)d_in[3];
    const float* bhh = (const float*)d_in[4];
    const float* W1  = (const float*)d_in[5];
    const float* b1  = (const float*)d_in[6];
    const float* W2  = (const float*)d_in[7];
    const float* b2  = (const float*)d_in[8];
    float* out = (float*)d_out;

    lstm_kernel<<<NGRID, NTH>>>(x, Wih, Whh, bih, bhh, W1, b1, W2, b2, out);
}

// round 6
// speedup vs baseline: 1.4355x; 1.0803x over previous
#include <cuda_runtime.h>

// LSTM B=1024 T=512 F=40 H=50 + MLP head, fused persistent kernel. Round 5.
//
// 256 CTAs x 256 threads, RR=4 batch rows per CTA, 2 CTAs co-resident per SM
// (regs capped at 128 -> 64K RF for 2x256 threads). Independent per-CTA
// barriers let one CTA's gemv phase overlap the other's cell/barrier phase.
//
//   tid 0..199   : gate thread j. Holds the FULL combined row W[j][0..91]
//                  ([W_ih | W_hh | pad], K padded 90->92) as 46 packed f32x2
//                  registers. Per step computes gate j for all 4 rows with
//                  fma.rn.f32x2 against broadcast ld.shared.v2.u64 of
//                  z = [x_t | h_{t-1}]. Bias folded into accumulator init.
//                  Writes gates directly to sG (no partial reduction).
//                  Then as cell thread (r=tid/50, u=tid%50): activations
//                  (MUFU tanh.approx), register-resident c, h -> sZ.
//   tid 200..239 : x prefetchers (4 rows x 10 float4), 2 steps ahead.
// Two __syncthreads per step.

#define TT   512
#define FF   40
#define HH   50
#define GG   200          // 4*H
#define RR   4            // rows per CTA
#define KP   92           // padded combined K (40 x | 50 h | 2 pad) = 23 f4
#define NC   200          // compute threads
#define NTH  256
#define NGRID 256         // 1024 / RR

__device__ __forceinline__ unsigned long long pk2(float lo, float hi) {
    unsigned long long r;
    asm("mov.b64 %0, {%1, %2};" : "=l"(r) : "f"(lo), "f"(hi));
    return r;
}
__device__ __forceinline__ void upk2(unsigned long long v, float& lo, float& hi) {
    asm("mov.b64 {%0, %1}, %2;" : "=f"(lo), "=f"(hi) : "l"(v));
}
__device__ __forceinline__ unsigned long long f2fma(unsigned long long a,
                                                   unsigned long long b,
                                                   unsigned long long c) {
    unsigned long long d;
    asm("fma.rn.f32x2 %0, %1, %2, %3;" : "=l"(d) : "l"(a), "l"(b), "l"(c));
    return d;
}
__device__ __forceinline__ float tanh_f(float x) {
    float y;
    asm("tanh.approx.f32 %0, %1;" : "=f"(y) : "f"(x));
    return y;
}
__device__ __forceinline__ float sig_f(float x) {
    return fmaf(0.5f, tanh_f(0.5f * x), 0.5f);   // sigmoid(x)=0.5*tanh(x/2)+0.5
}
__device__ __forceinline__ float wfetch(const float* __restrict__ Wih,
                                        const float* __restrict__ Whh,
                                        int j, int k) {
    if (k < FF)       return Wih[j * FF + k];
    if (k < FF + HH)  return Whh[j * HH + (k - FF)];
    return 0.0f;
}

__global__ __launch_bounds__(NTH, 2)
void lstm_kernel(const float* __restrict__ x,   const float* __restrict__ Wih,
                 const float* __restrict__ Whh, const float* __restrict__ bih,
                 const float* __restrict__ bhh, const float* __restrict__ W1,
                 const float* __restrict__ b1,  const float* __restrict__ W2,
                 const float* __restrict__ b2,  float* __restrict__ out)
{
    __shared__ __align__(16) float sZ[RR][KP];    // z = [x_t | h | pad]
    __shared__ __align__(16) float sG[RR][GG];    // pre-activation gates

    const int tid = threadIdx.x;
    const int b0  = blockIdx.x * RR;

    // ---- zero z (h + pads; x region overwritten below) ----
    for (int i = tid; i < RR * KP; i += NTH) ((float*)sZ)[i] = 0.0f;
    __syncthreads();

    // ---- register-resident full-K weights (packed f32x2) + folded bias ----
    const int j = (tid < NC) ? tid : 0;
    unsigned long long w[46];
    #pragma unroll
    for (int kk = 0; kk < 46; ++kk) {
        float lo = (tid < NC) ? wfetch(Wih, Whh, j, 2 * kk)     : 0.0f;
        float hi = (tid < NC) ? wfetch(Wih, Whh, j, 2 * kk + 1) : 0.0f;
        w[kk] = pk2(lo, hi);
    }
    const unsigned long long bias0 =
        (tid < NC) ? pk2(bih[j] + bhh[j], 0.0f) : 0ull;

    // ---- cell role: (cr, cu); c0[:,0] = 1, register-resident ----
    const int cr = tid / HH;
    const int cu = tid - cr * HH;
    float creg = (tid < NC && cu == 0) ? 1.0f : 0.0f;

    // ---- x prefetch roles: tid 200..239 own one (row, float4) slot ----
    const int li = tid - NC;
    const int lr = li / 10, lq = li - (li / 10) * 10;
    const bool isload = (tid >= NC) && (li < RR * 10);
    const float4* __restrict__ xv = (const float4*)x;
    float4 xn = make_float4(0.f, 0.f, 0.f, 0.f);
    if (isload) {
        ((float4*)&sZ[lr][0])[lq] = xv[((b0 + lr) * TT + 0) * 10 + lq];  // x_0
        xn = xv[((b0 + lr) * TT + 1) * 10 + lq];                          // x_1
    }
    __syncthreads();

    // ================= recurrence =================
    for (int t = 0; t < TT; ++t) {
        // Phase A: gate j for 4 rows, full K, register weights
        if (tid < NC) {
            unsigned long long a0 = bias0, a1 = bias0, a2 = bias0, a3 = bias0;
            const ulonglong2* __restrict__ zb = (const ulonglong2*)&sZ[0][0];
            #pragma unroll
            for (int i = 0; i < 23; ++i) {                 // 23 ull2 per row
                ulonglong2 z0 = zb[ 0 + i];
                ulonglong2 z1 = zb[23 + i];
                ulonglong2 z2 = zb[46 + i];
                ulonglong2 z3 = zb[69 + i];
                unsigned long long wa = w[2 * i], wb = w[2 * i + 1];
                a0 = f2fma(wa, z0.x, a0); a0 = f2fma(wb, z0.y, a0);
                a1 = f2fma(wa, z1.x, a1); a1 = f2fma(wb, z1.y, a1);
                a2 = f2fma(wa, z2.x, a2); a2 = f2fma(wb, z2.y, a2);
                a3 = f2fma(wa, z3.x, a3); a3 = f2fma(wb, z3.y, a3);
            }
            float lo, hi;
            upk2(a0, lo, hi); sG[0][tid] = lo + hi;
            upk2(a1, lo, hi); sG[1][tid] = lo + hi;
            upk2(a2, lo, hi); sG[2][tid] = lo + hi;
            upk2(a3, lo, hi); sG[3][tid] = lo + hi;
        }
        __syncthreads();

        // Phase B: cell update (200 threads) + x commit/prefetch (40 threads)
        if (tid < NC) {
            float gi = sG[cr][         cu];
            float gf = sG[cr][    HH + cu];
            float gc = sG[cr][2 * HH + cu];
            float go = sG[cr][3 * HH + cu];
            float si = sig_f(gi);
            float sf = sig_f(gf);
            float tg = tanh_f(gc);
            float so = sig_f(go);
            creg = fmaf(sf, creg, si * tg);
            sZ[cr][FF + cu] = so * tanh_f(creg);
        } else if (isload && (t + 1) < TT) {
            ((float4*)&sZ[lr][0])[lq] = xn;                // commit x_{t+1}
            if ((t + 2) < TT)
                xn = xv[((b0 + lr) * TT + (t + 2)) * 10 + lq];
        }
        __syncthreads();
    }

    // ================= MLP head =================
    if (tid < RR * 10) {        // hidden[r][m] = relu(b1 + h.W1[m])
        int r = tid / 10, m = tid - (tid / 10) * 10;
        float s = b1[m];
        #pragma unroll
        for (int u = 0; u < HH; ++u)
            s = fmaf(sZ[r][FF + u], W1[m * HH + u], s);
        sG[0][tid] = fmaxf(s, 0.0f);
    }
    __syncthreads();

    if (tid < RR) {             // out[b] = b2 + hidden.W2 + x[b, T-1, 0]
        float o = b2[0];
        #pragma unroll
        for (int m = 0; m < 10; ++m)
            o = fmaf(sG[0][tid * 10 + m], W2[m], o);
        out[b0 + tid] = o + x[((b0 + tid) * TT + (TT - 1)) * FF + 0];
    }
}

extern "C" void kernel_launch(void* const* d_in, const int* in_sizes, int n_in,
                              void* d_out, int out_size)
{
    const float* x   = (const float*)d_in[0];
    const float* Wih = (const float*)d_in[1];
    const float* Whh = (const float*)d_in[2];
    const float* bih = (const float*)d_in[3];
    const float* bhh = (const float*)d_in[4];
    const float* W1  = (const float*)d_in[5];
    const float* b1  = (const float*)d_in[6];
    const float* W2  = (const float*)d_in[7];
    const float* b2  = (const float*)d_in[8];
    float* out = (float*)d_out;

    lstm_kernel<<<NGRID, NTH>>>(x, Wih, Whh, bih, bhh, W1, b1, W2, b2, out);
}